// round 1
// baseline (speedup 1.0000x reference)
#include <cuda_runtime.h>
#include <math.h>

#define B_   8
#define T_   1024
#define E_   1024
#define H_   16
#define D_   64
#define BH_  (B_*H_)   /* 128 */
#define M_   (B_*T_)   /* 8192 */

// ---------------- device scratch (no allocations allowed) ----------------
__device__ float g_Q[(size_t)BH_ * T_ * D_];   // 32 MB, head-split [bh, t, d]
__device__ float g_K[(size_t)BH_ * T_ * D_];
__device__ float g_V[(size_t)BH_ * T_ * D_];
__device__ float g_C[(size_t)M_ * E_];         // merged context [b*t, e]

// ---------------- SGEMM: out = (X @ W^T + bias) * alpha ----------------
// X: [M_, 1024] row-major, W: [1024, 1024] row-major, bias: [1024]
// split_heads=1 writes out[(b*H + n/64)*T + t][n%64] (head-split layout)
#define BM 128
#define BN 128
#define BK 16

__global__ __launch_bounds__(256) void sgemm_kernel(
    const float* __restrict__ X, const float* __restrict__ W,
    const float* __restrict__ bias, float* __restrict__ out,
    float alpha, int split_heads)
{
    __shared__ float As[BK][BM];
    __shared__ float Bs[BK][BN];
    const int tid = threadIdx.x;
    const int m0 = blockIdx.y * BM;
    const int n0 = blockIdx.x * BN;
    const int tr = tid >> 4;   // 0..15
    const int tc = tid & 15;   // 0..15

    float acc[8][8];
    #pragma unroll
    for (int i = 0; i < 8; i++)
        #pragma unroll
        for (int j = 0; j < 8; j++) acc[i][j] = 0.f;

    for (int k0 = 0; k0 < E_; k0 += BK) {
        // load 128x16 tiles of X and W (transposed into smem)
        #pragma unroll
        for (int i = 0; i < 2; i++) {
            int idx = tid + i * 256;          // 0..511
            int row = idx >> 2;               // 0..127
            int c4  = (idx & 3) << 2;         // 0,4,8,12
            float4 va = *reinterpret_cast<const float4*>(
                &X[(size_t)(m0 + row) * E_ + k0 + c4]);
            As[c4 + 0][row] = va.x; As[c4 + 1][row] = va.y;
            As[c4 + 2][row] = va.z; As[c4 + 3][row] = va.w;
            float4 vb = *reinterpret_cast<const float4*>(
                &W[(size_t)(n0 + row) * E_ + k0 + c4]);
            Bs[c4 + 0][row] = vb.x; Bs[c4 + 1][row] = vb.y;
            Bs[c4 + 2][row] = vb.z; Bs[c4 + 3][row] = vb.w;
        }
        __syncthreads();

        #pragma unroll
        for (int kk = 0; kk < BK; kk++) {
            float a[8], b[8];
            float4 a0 = *reinterpret_cast<const float4*>(&As[kk][tr * 8]);
            float4 a1 = *reinterpret_cast<const float4*>(&As[kk][tr * 8 + 4]);
            float4 b0 = *reinterpret_cast<const float4*>(&Bs[kk][tc * 8]);
            float4 b1 = *reinterpret_cast<const float4*>(&Bs[kk][tc * 8 + 4]);
            a[0]=a0.x; a[1]=a0.y; a[2]=a0.z; a[3]=a0.w;
            a[4]=a1.x; a[5]=a1.y; a[6]=a1.z; a[7]=a1.w;
            b[0]=b0.x; b[1]=b0.y; b[2]=b0.z; b[3]=b0.w;
            b[4]=b1.x; b[5]=b1.y; b[6]=b1.z; b[7]=b1.w;
            #pragma unroll
            for (int i = 0; i < 8; i++)
                #pragma unroll
                for (int j = 0; j < 8; j++)
                    acc[i][j] += a[i] * b[j];
        }
        __syncthreads();
    }

    #pragma unroll
    for (int i = 0; i < 8; i++) {
        int m  = m0 + tr * 8 + i;
        int bb = m >> 10;        // / 1024
        int t  = m & 1023;
        #pragma unroll
        for (int j = 0; j < 8; j++) {
            int n = n0 + tc * 8 + j;
            float v = (acc[i][j] + bias[n]) * alpha;
            if (split_heads) {
                int h = n >> 6, d = n & 63;
                out[(((size_t)(bb * H_ + h)) * T_ + t) * D_ + d] = v;
            } else {
                out[(size_t)m * E_ + n] = v;
            }
        }
    }
}

// ---------------- XPos rotary (applied in-place to g_Q and g_K) ----------------
// one thread per (bh, t, pair j); handles both q (upscale) and k (downscale)
__global__ __launch_bounds__(256) void xpos_kernel()
{
    int idx = blockIdx.x * blockDim.x + threadIdx.x;
    if (idx >= BH_ * T_ * (D_ / 2)) return;
    int j  = idx & 31;
    int t  = (idx >> 5) & 1023;
    int bh = idx >> 15;

    float sj    = (2.f * j + 0.4f * (float)D_) / (1.4f * (float)D_);
    float pos   = (float)t - (float)(T_ / 2);
    float scale = powf(sj, pos * (1.f / (float)E_));   // SCALE_BASE = 1024
    float invf  = powf(10000.f, -(float)j / 32.f);
    float sn, cs;
    sincosf((float)t * invf, &sn, &cs);

    size_t base = ((size_t)bh * T_ + t) * D_ + 2 * j;

    // q: downscale=False -> multiply by scale
    float cq = cs * scale, sq = sn * scale;
    float x1 = g_Q[base], x2 = g_Q[base + 1];
    g_Q[base]     = x1 * cq - x2 * sq;
    g_Q[base + 1] = x2 * cq + x1 * sq;

    // k: downscale=True -> multiply by 1/scale
    float inv = 1.f / scale;
    float ck = cs * inv, sk = sn * inv;
    x1 = g_K[base]; x2 = g_K[base + 1];
    g_K[base]     = x1 * ck - x2 * sk;
    g_K[base + 1] = x2 * ck + x1 * sk;
}

// ---------------- Flash attention (fp32, online softmax) ----------------
// block = (bh, tile of 128 t-rows); thread owns one t-row.
// q[64], o[64], scores[32] live in registers; K/V 32x64 tiles in smem
// (reads are warp-uniform -> broadcast, conflict-free).
#define ATT_TT 128
#define ATT_ST 32

__global__ __launch_bounds__(128) void attn_kernel()
{
    __shared__ float Ks[ATT_ST][D_];
    __shared__ float Vs[ATT_ST][D_];
    const int bh  = blockIdx.x;
    const int tid = threadIdx.x;
    const int t   = blockIdx.y * ATT_TT + tid;

    float q[D_];
    const float* qptr = &g_Q[((size_t)bh * T_ + t) * D_];
    #pragma unroll
    for (int d = 0; d < D_; d += 4) {
        float4 v = *reinterpret_cast<const float4*>(qptr + d);
        q[d] = v.x; q[d + 1] = v.y; q[d + 2] = v.z; q[d + 3] = v.w;
    }
    float o[D_];
    #pragma unroll
    for (int d = 0; d < D_; d++) o[d] = 0.f;
    float mrun = -1e30f, lrun = 0.f;

    for (int s0 = 0; s0 < T_; s0 += ATT_ST) {
        // load K/V tiles: 32*64 floats each, 4 float4 per thread
        #pragma unroll
        for (int i = 0; i < (ATT_ST * D_ / 4) / 128; i++) {
            int idx = tid + i * 128;
            int r = idx >> 4;
            int c = (idx & 15) << 2;
            size_t g = ((size_t)bh * T_ + s0 + r) * D_ + c;
            *reinterpret_cast<float4*>(&Ks[r][c]) =
                *reinterpret_cast<const float4*>(&g_K[g]);
            *reinterpret_cast<float4*>(&Vs[r][c]) =
                *reinterpret_cast<const float4*>(&g_V[g]);
        }
        __syncthreads();

        float sc[ATT_ST];
        float smax = mrun;
        #pragma unroll
        for (int s = 0; s < ATT_ST; s++) {
            float a0 = 0.f, a1 = 0.f, a2 = 0.f, a3 = 0.f;
            #pragma unroll
            for (int d = 0; d < D_; d += 4) {
                a0 += q[d + 0] * Ks[s][d + 0];
                a1 += q[d + 1] * Ks[s][d + 1];
                a2 += q[d + 2] * Ks[s][d + 2];
                a3 += q[d + 3] * Ks[s][d + 3];
            }
            float dot = (a0 + a1) + (a2 + a3);
            sc[s] = dot;
            smax = fmaxf(smax, dot);
        }

        float corr = __expf(mrun - smax);
        lrun *= corr;
        #pragma unroll
        for (int d = 0; d < D_; d++) o[d] *= corr;

        #pragma unroll
        for (int s = 0; s < ATT_ST; s++) {
            float p = __expf(sc[s] - smax);
            sc[s] = p;
            lrun += p;
        }
        mrun = smax;

        #pragma unroll
        for (int s = 0; s < ATT_ST; s++) {
            float p = sc[s];
            #pragma unroll
            for (int d = 0; d < D_; d++) o[d] += p * Vs[s][d];
        }
        __syncthreads();
    }

    const float inv_l = 1.f / lrun;
    const int b = bh >> 4, h = bh & 15;
    float* cptr = &g_C[((size_t)(b * T_ + t)) * E_ + h * D_];
    #pragma unroll
    for (int d = 0; d < D_; d += 4) {
        float4 v = make_float4(o[d] * inv_l, o[d + 1] * inv_l,
                               o[d + 2] * inv_l, o[d + 3] * inv_l);
        *reinterpret_cast<float4*>(cptr + d) = v;
    }
}

// ---------------- launch ----------------
extern "C" void kernel_launch(void* const* d_in, const int* in_sizes, int n_in,
                              void* d_out, int out_size)
{
    const float* query = (const float*)d_in[0];
    const float* key   = (const float*)d_in[1];
    const float* value = (const float*)d_in[2];
    const float* wq    = (const float*)d_in[3];
    const float* bq    = (const float*)d_in[4];
    const float* wk    = (const float*)d_in[5];
    const float* bk    = (const float*)d_in[6];
    const float* wv    = (const float*)d_in[7];
    const float* bv    = (const float*)d_in[8];
    const float* wo    = (const float*)d_in[9];
    const float* bo    = (const float*)d_in[10];
    float* out = (float*)d_out;

    float *Q, *K, *V, *C;
    cudaGetSymbolAddress((void**)&Q, g_Q);
    cudaGetSymbolAddress((void**)&K, g_K);
    cudaGetSymbolAddress((void**)&V, g_V);
    cudaGetSymbolAddress((void**)&C, g_C);

    dim3 gemm_grid(E_ / BN, M_ / BM);   // (8, 64)
    const float scaling = 0.125f;       // HEAD_DIM^-0.5

    sgemm_kernel<<<gemm_grid, 256>>>(query, wq, bq, Q, scaling, 1);
    sgemm_kernel<<<gemm_grid, 256>>>(key,   wk, bk, K, 1.f, 1);
    sgemm_kernel<<<gemm_grid, 256>>>(value, wv, bv, V, 1.f, 1);

    int xpos_threads = BH_ * T_ * (D_ / 2);   // 4,194,304
    xpos_kernel<<<xpos_threads / 256, 256>>>();

    attn_kernel<<<dim3(BH_, T_ / ATT_TT), 128>>>();

    sgemm_kernel<<<gemm_grid, 256>>>(C, wo, bo, out, 1.f, 0);
}

// round 3
// speedup vs baseline: 1.5216x; 1.5216x over previous
#include <cuda_runtime.h>
#include <cuda_bf16.h>
#include <math.h>
#include <cstdint>

#define B_   8
#define T_   1024
#define E_   1024
#define H_   16
#define D_   64
#define BH_  (B_*H_)   /* 128 */
#define M_   (B_*T_)   /* 8192 */

// ---------------- device scratch (no allocations allowed) ----------------
__device__ float g_Q[(size_t)BH_ * T_ * D_];   // 32 MB, head-split [bh, t, d]
__device__ float g_K[(size_t)BH_ * T_ * D_];
__device__ float g_V[(size_t)BH_ * T_ * D_];
__device__ float g_C[(size_t)M_ * E_];         // merged context [b*t, e]

__device__ __align__(256) __nv_bfloat16 g_Xhi[(size_t)M_ * E_];  // 16 MB
__device__ __align__(256) __nv_bfloat16 g_Xlo[(size_t)M_ * E_];
__device__ __align__(256) __nv_bfloat16 g_Whi[(size_t)E_ * E_];  // 2 MB
__device__ __align__(256) __nv_bfloat16 g_Wlo[(size_t)E_ * E_];

// ================= PTX helpers (base-arch only: LDSM/HMMA/LDGSTS) =================
__device__ __forceinline__ uint32_t smem_u32(const void* p) {
    uint32_t a;
    asm("{ .reg .u64 t; cvta.to.shared.u64 t, %1; cvt.u32.u64 %0, t; }" : "=r"(a) : "l"(p));
    return a;
}
__device__ __forceinline__ void ldsm_x4(uint32_t& r0, uint32_t& r1, uint32_t& r2, uint32_t& r3,
                                        uint32_t addr) {
    asm volatile("ldmatrix.sync.aligned.m8n8.x4.shared.b16 {%0,%1,%2,%3}, [%4];"
                 : "=r"(r0), "=r"(r1), "=r"(r2), "=r"(r3) : "r"(addr));
}
__device__ __forceinline__ void mma_bf16(float* d, const uint32_t* a, const uint32_t* b) {
    asm volatile(
        "mma.sync.aligned.m16n8k16.row.col.f32.bf16.bf16.f32 "
        "{%0,%1,%2,%3}, {%4,%5,%6,%7}, {%8,%9}, {%0,%1,%2,%3};"
        : "+f"(d[0]), "+f"(d[1]), "+f"(d[2]), "+f"(d[3])
        : "r"(a[0]), "r"(a[1]), "r"(a[2]), "r"(a[3]), "r"(b[0]), "r"(b[1]));
}
#define CP_ASYNC16(dst, src) \
    asm volatile("cp.async.cg.shared.global [%0], [%1], 16;" :: "r"(dst), "l"(src))
#define CP_COMMIT() asm volatile("cp.async.commit_group;" ::: "memory")
#define CP_WAIT0()  asm volatile("cp.async.wait_group 0;" ::: "memory")

// ================= fp32 -> bf16 hi/lo split kernel =================
__global__ __launch_bounds__(256) void split_kernel(
    const float* __restrict__ x, __nv_bfloat16* __restrict__ hi,
    __nv_bfloat16* __restrict__ lo, int n8)
{
    int idx = blockIdx.x * blockDim.x + threadIdx.x;
    if (idx >= n8) return;
    float4 v0 = *reinterpret_cast<const float4*>(x + (size_t)idx * 8);
    float4 v1 = *reinterpret_cast<const float4*>(x + (size_t)idx * 8 + 4);
    float v[8] = {v0.x, v0.y, v0.z, v0.w, v1.x, v1.y, v1.z, v1.w};
    __nv_bfloat16 hs[8], ls[8];
    #pragma unroll
    for (int i = 0; i < 8; i++) {
        hs[i] = __float2bfloat16(v[i]);
        ls[i] = __float2bfloat16(v[i] - __bfloat162float(hs[i]));
    }
    *reinterpret_cast<uint4*>(hi + (size_t)idx * 8) = *reinterpret_cast<uint4*>(hs);
    *reinterpret_cast<uint4*>(lo + (size_t)idx * 8) = *reinterpret_cast<uint4*>(ls);
}

// ================= mma.sync GEMM: out = (X @ W^T + bias) * alpha =================
// Effective K' = 3*1024: phases (Xhi*Whi) + (Xhi*Wlo) + (Xlo*Whi).
// Block 256 thr = 8 warps; tile 128x128; warp tile 64(m) x 32(n); BK=32.
// smem rows padded to 40 bf16 (80B) -> conflict-free ldmatrix.
#define BKC      32
#define ROWB     80        /* bytes per padded smem row */
#define TILE_B   (128 * ROWB)  /* 10240 B per tile */
#define N_CHUNKS 96        /* 3 phases * (1024/32) */

__global__ __launch_bounds__(256) void gemm_mma(
    const __nv_bfloat16* __restrict__ Xhi, const __nv_bfloat16* __restrict__ Xlo,
    const __nv_bfloat16* __restrict__ Whi, const __nv_bfloat16* __restrict__ Wlo,
    const float* __restrict__ bias, float* __restrict__ out,
    float alpha, int split_heads)
{
    __shared__ __align__(16) char sA[2 * TILE_B];
    __shared__ __align__(16) char sB[2 * TILE_B];
    const uint32_t sAb = smem_u32(sA);
    const uint32_t sBb = smem_u32(sB);

    const int tid  = threadIdx.x;
    const int wid  = tid >> 5;
    const int lane = tid & 31;
    const int m0 = blockIdx.y * 128;
    const int n0 = blockIdx.x * 128;
    const int m_w = (wid & 1) * 64;    // warp m offset
    const int n_w = (wid >> 1) * 32;   // warp n offset

    // loader indices: 2 segs per tile per thread
    const int l_row0 = tid >> 2;            // 0..63
    const int l_cs   = (tid & 3);           // 0..3 -> 16B seg
    const uint32_t l_soff0 = (uint32_t)l_row0 * ROWB + l_cs * 16;
    const uint32_t l_soff1 = (uint32_t)(l_row0 + 64) * ROWB + l_cs * 16;
    const int l_goff = l_cs * 8;             // bf16 col offset

    float acc[4][4][4];
    #pragma unroll
    for (int i = 0; i < 4; i++)
        #pragma unroll
        for (int j = 0; j < 4; j++)
            #pragma unroll
            for (int q = 0; q < 4; q++) acc[i][j][q] = 0.f;

    // ldmatrix address components (within a tile)
    const uint32_t a_ld_base = (uint32_t)(m_w + (lane & 15)) * ROWB + (lane >> 4) * 16;
    const int bg = lane >> 3;                 // 0..3
    const uint32_t b_ld_row = (uint32_t)(n_w + ((bg >> 1) * 8) + (lane & 7)) * ROWB;
    const uint32_t b_ld_col = (uint32_t)(bg & 1) * 16;

    // prologue: load chunk 0 into buf 0
    {
        const __nv_bfloat16* sa = Xhi + (size_t)m0 * E_;
        const __nv_bfloat16* sb = Whi + (size_t)n0 * E_;
        CP_ASYNC16(sAb + l_soff0, sa + (size_t)l_row0 * E_ + l_goff);
        CP_ASYNC16(sAb + l_soff1, sa + (size_t)(l_row0 + 64) * E_ + l_goff);
        CP_ASYNC16(sBb + l_soff0, sb + (size_t)l_row0 * E_ + l_goff);
        CP_ASYNC16(sBb + l_soff1, sb + (size_t)(l_row0 + 64) * E_ + l_goff);
        CP_COMMIT();
        CP_WAIT0();
        __syncthreads();
    }

    for (int it = 0; it < N_CHUNKS; ++it) {
        const int buf = it & 1;

        // issue loads for chunk it+1 into buf^1
        if (it + 1 < N_CHUNKS) {
            const int nit = it + 1;
            const int p  = nit >> 5;              // 32 chunks per phase
            const int kc = (nit & 31) * BKC;
            const __nv_bfloat16* sa = ((p == 2) ? Xlo : Xhi) + (size_t)m0 * E_ + kc;
            const __nv_bfloat16* sb = ((p == 1) ? Wlo : Whi) + (size_t)n0 * E_ + kc;
            const uint32_t ab = sAb + (buf ^ 1) * TILE_B;
            const uint32_t bb = sBb + (buf ^ 1) * TILE_B;
            CP_ASYNC16(ab + l_soff0, sa + (size_t)l_row0 * E_ + l_goff);
            CP_ASYNC16(ab + l_soff1, sa + (size_t)(l_row0 + 64) * E_ + l_goff);
            CP_ASYNC16(bb + l_soff0, sb + (size_t)l_row0 * E_ + l_goff);
            CP_ASYNC16(bb + l_soff1, sb + (size_t)(l_row0 + 64) * E_ + l_goff);
            CP_COMMIT();
        }

        // compute on buf: 2 k-steps of 16
        const uint32_t at = sAb + buf * TILE_B;
        const uint32_t bt = sBb + buf * TILE_B;
        #pragma unroll
        for (int ks = 0; ks < 2; ks++) {
            uint32_t af[4][4];
            #pragma unroll
            for (int mf = 0; mf < 4; mf++)
                ldsm_x4(af[mf][0], af[mf][1], af[mf][2], af[mf][3],
                        at + a_ld_base + (uint32_t)mf * 16 * ROWB + ks * 32);
            uint32_t bf[4][2];
            #pragma unroll
            for (int nf2 = 0; nf2 < 2; nf2++) {
                uint32_t r0, r1, r2, r3;
                ldsm_x4(r0, r1, r2, r3,
                        bt + b_ld_row + (uint32_t)nf2 * 16 * ROWB + b_ld_col + ks * 32);
                bf[nf2 * 2 + 0][0] = r0; bf[nf2 * 2 + 0][1] = r1;
                bf[nf2 * 2 + 1][0] = r2; bf[nf2 * 2 + 1][1] = r3;
            }
            #pragma unroll
            for (int mf = 0; mf < 4; mf++)
                #pragma unroll
                for (int nf = 0; nf < 4; nf++)
                    mma_bf16(acc[mf][nf], af[mf], bf[nf]);
        }

        CP_WAIT0();
        __syncthreads();
    }

    // epilogue
    #pragma unroll
    for (int mf = 0; mf < 4; mf++) {
        #pragma unroll
        for (int half = 0; half < 2; half++) {
            const int m = m0 + m_w + mf * 16 + (lane >> 2) + half * 8;
            const int bb = m >> 10;
            const int t  = m & 1023;
            #pragma unroll
            for (int nf = 0; nf < 4; nf++) {
                const int n = n0 + n_w + nf * 8 + (lane & 3) * 2;
                float2 v;
                v.x = (acc[mf][nf][half * 2 + 0] + __ldg(bias + n)) * alpha;
                v.y = (acc[mf][nf][half * 2 + 1] + __ldg(bias + n + 1)) * alpha;
                if (split_heads) {
                    const int h = n >> 6, d = n & 63;
                    *reinterpret_cast<float2*>(
                        out + (((size_t)(bb * H_ + h)) * T_ + t) * D_ + d) = v;
                } else {
                    *reinterpret_cast<float2*>(out + (size_t)m * E_ + n) = v;
                }
            }
        }
    }
}

// ---------------- XPos rotary (applied in-place to g_Q and g_K) ----------------
__global__ __launch_bounds__(256) void xpos_kernel()
{
    int idx = blockIdx.x * blockDim.x + threadIdx.x;
    if (idx >= BH_ * T_ * (D_ / 2)) return;
    int j  = idx & 31;
    int t  = (idx >> 5) & 1023;
    int bh = idx >> 15;

    float sj    = (2.f * j + 0.4f * (float)D_) / (1.4f * (float)D_);
    float pos   = (float)t - (float)(T_ / 2);
    float scale = powf(sj, pos * (1.f / (float)E_));   // SCALE_BASE = 1024
    float invf  = powf(10000.f, -(float)j / 32.f);
    float sn, cs;
    sincosf((float)t * invf, &sn, &cs);

    size_t base = ((size_t)bh * T_ + t) * D_ + 2 * j;

    float cq = cs * scale, sq = sn * scale;
    float x1 = g_Q[base], x2 = g_Q[base + 1];
    g_Q[base]     = x1 * cq - x2 * sq;
    g_Q[base + 1] = x2 * cq + x1 * sq;

    float inv = 1.f / scale;
    float ck = cs * inv, sk = sn * inv;
    x1 = g_K[base]; x2 = g_K[base + 1];
    g_K[base]     = x1 * ck - x2 * sk;
    g_K[base + 1] = x2 * ck + x1 * sk;
}

// ---------------- Flash attention (fp32, online softmax) ----------------
#define ATT_TT 128
#define ATT_ST 32

__global__ __launch_bounds__(128) void attn_kernel()
{
    __shared__ float Ks[ATT_ST][D_];
    __shared__ float Vs[ATT_ST][D_];
    const int bh  = blockIdx.x;
    const int tid = threadIdx.x;
    const int t   = blockIdx.y * ATT_TT + tid;

    float q[D_];
    const float* qptr = &g_Q[((size_t)bh * T_ + t) * D_];
    #pragma unroll
    for (int d = 0; d < D_; d += 4) {
        float4 v = *reinterpret_cast<const float4*>(qptr + d);
        q[d] = v.x; q[d + 1] = v.y; q[d + 2] = v.z; q[d + 3] = v.w;
    }
    float o[D_];
    #pragma unroll
    for (int d = 0; d < D_; d++) o[d] = 0.f;
    float mrun = -1e30f, lrun = 0.f;

    for (int s0 = 0; s0 < T_; s0 += ATT_ST) {
        #pragma unroll
        for (int i = 0; i < (ATT_ST * D_ / 4) / 128; i++) {
            int idx = tid + i * 128;
            int r = idx >> 4;
            int c = (idx & 15) << 2;
            size_t g = ((size_t)bh * T_ + s0 + r) * D_ + c;
            *reinterpret_cast<float4*>(&Ks[r][c]) =
                *reinterpret_cast<const float4*>(&g_K[g]);
            *reinterpret_cast<float4*>(&Vs[r][c]) =
                *reinterpret_cast<const float4*>(&g_V[g]);
        }
        __syncthreads();

        float sc[ATT_ST];
        float smax = mrun;
        #pragma unroll
        for (int s = 0; s < ATT_ST; s++) {
            float a0 = 0.f, a1 = 0.f, a2 = 0.f, a3 = 0.f;
            #pragma unroll
            for (int d = 0; d < D_; d += 4) {
                a0 += q[d + 0] * Ks[s][d + 0];
                a1 += q[d + 1] * Ks[s][d + 1];
                a2 += q[d + 2] * Ks[s][d + 2];
                a3 += q[d + 3] * Ks[s][d + 3];
            }
            float dot = (a0 + a1) + (a2 + a3);
            sc[s] = dot;
            smax = fmaxf(smax, dot);
        }

        float corr = __expf(mrun - smax);
        lrun *= corr;
        #pragma unroll
        for (int d = 0; d < D_; d++) o[d] *= corr;

        #pragma unroll
        for (int s = 0; s < ATT_ST; s++) {
            float p = __expf(sc[s] - smax);
            sc[s] = p;
            lrun += p;
        }
        mrun = smax;

        #pragma unroll
        for (int s = 0; s < ATT_ST; s++) {
            float p = sc[s];
            #pragma unroll
            for (int d = 0; d < D_; d++) o[d] += p * Vs[s][d];
        }
        __syncthreads();
    }

    const float inv_l = 1.f / lrun;
    const int b = bh >> 4, h = bh & 15;
    float* cptr = &g_C[((size_t)(b * T_ + t)) * E_ + h * D_];
    #pragma unroll
    for (int d = 0; d < D_; d += 4) {
        float4 v = make_float4(o[d] * inv_l, o[d + 1] * inv_l,
                               o[d + 2] * inv_l, o[d + 3] * inv_l);
        *reinterpret_cast<float4*>(cptr + d) = v;
    }
}

// ---------------- launch ----------------
extern "C" void kernel_launch(void* const* d_in, const int* in_sizes, int n_in,
                              void* d_out, int out_size)
{
    const float* query = (const float*)d_in[0];
    const float* key   = (const float*)d_in[1];
    const float* value = (const float*)d_in[2];
    const float* wq    = (const float*)d_in[3];
    const float* bq    = (const float*)d_in[4];
    const float* wk    = (const float*)d_in[5];
    const float* bk    = (const float*)d_in[6];
    const float* wv    = (const float*)d_in[7];
    const float* bv    = (const float*)d_in[8];
    const float* wo    = (const float*)d_in[9];
    const float* bo    = (const float*)d_in[10];
    float* out = (float*)d_out;

    float *Q, *K, *V, *C;
    cudaGetSymbolAddress((void**)&Q, g_Q);
    cudaGetSymbolAddress((void**)&K, g_K);
    cudaGetSymbolAddress((void**)&V, g_V);
    cudaGetSymbolAddress((void**)&C, g_C);
    __nv_bfloat16 *Xhi, *Xlo, *Whi, *Wlo;
    cudaGetSymbolAddress((void**)&Xhi, g_Xhi);
    cudaGetSymbolAddress((void**)&Xlo, g_Xlo);
    cudaGetSymbolAddress((void**)&Whi, g_Whi);
    cudaGetSymbolAddress((void**)&Wlo, g_Wlo);

    dim3 gemm_grid(E_ / 128, M_ / 128);     // (8, 64)
    const int actn8 = (M_ * E_) / 8;        // 1,048,576
    const int wn8   = (E_ * E_) / 8;        // 131,072
    const float scaling = 0.125f;           // HEAD_DIM^-0.5

    // Q projection
    split_kernel<<<actn8 / 256, 256>>>(query, Xhi, Xlo, actn8);
    split_kernel<<<wn8 / 256, 256>>>(wq, Whi, Wlo, wn8);
    gemm_mma<<<gemm_grid, 256>>>(Xhi, Xlo, Whi, Wlo, bq, Q, scaling, 1);
    // K projection
    split_kernel<<<actn8 / 256, 256>>>(key, Xhi, Xlo, actn8);
    split_kernel<<<wn8 / 256, 256>>>(wk, Whi, Wlo, wn8);
    gemm_mma<<<gemm_grid, 256>>>(Xhi, Xlo, Whi, Wlo, bk, K, 1.f, 1);
    // V projection
    split_kernel<<<actn8 / 256, 256>>>(value, Xhi, Xlo, actn8);
    split_kernel<<<wn8 / 256, 256>>>(wv, Whi, Wlo, wn8);
    gemm_mma<<<gemm_grid, 256>>>(Xhi, Xlo, Whi, Wlo, bv, V, 1.f, 1);

    int xpos_threads = BH_ * T_ * (D_ / 2);   // 4,194,304
    xpos_kernel<<<xpos_threads / 256, 256>>>();

    attn_kernel<<<dim3(BH_, T_ / ATT_TT), 128>>>();

    // output projection
    split_kernel<<<actn8 / 256, 256>>>(C, Xhi, Xlo, actn8);
    split_kernel<<<wn8 / 256, 256>>>(wo, Whi, Wlo, wn8);
    gemm_mma<<<gemm_grid, 256>>>(Xhi, Xlo, Whi, Wlo, bo, out, 1.f, 0);
}

// round 4
// speedup vs baseline: 2.7791x; 1.8265x over previous
#include <cuda_runtime.h>
#include <cuda_bf16.h>
#include <math.h>
#include <cstdint>

#define B_   8
#define T_   1024
#define E_   1024
#define H_   16
#define D_   64
#define BH_  (B_*H_)   /* 128 */
#define M_   (B_*T_)   /* 8192 */

// ---------------- device scratch (no allocations allowed) ----------------
__device__ float g_Q[(size_t)BH_ * T_ * D_];   // fp32 head-split [bh, t, d]
__device__ float g_K[(size_t)BH_ * T_ * D_];
__device__ float g_V[(size_t)BH_ * T_ * D_];
__device__ float g_C[(size_t)M_ * E_];         // merged context [b*t, e]

__device__ __align__(256) __nv_bfloat16 g_Xhi[(size_t)M_ * E_];
__device__ __align__(256) __nv_bfloat16 g_Xlo[(size_t)M_ * E_];
__device__ __align__(256) __nv_bfloat16 g_Whi[(size_t)E_ * E_];
__device__ __align__(256) __nv_bfloat16 g_Wlo[(size_t)E_ * E_];

// attention bf16 operands (post-xpos), head-split
__device__ __align__(256) __nv_bfloat16 g_Qhi[(size_t)BH_ * T_ * D_];
__device__ __align__(256) __nv_bfloat16 g_Qlo[(size_t)BH_ * T_ * D_];
__device__ __align__(256) __nv_bfloat16 g_Khi[(size_t)BH_ * T_ * D_];
__device__ __align__(256) __nv_bfloat16 g_Klo[(size_t)BH_ * T_ * D_];
__device__ __align__(256) __nv_bfloat16 g_Vthi[(size_t)BH_ * D_ * T_];  // [bh, d, s]
__device__ __align__(256) __nv_bfloat16 g_Vtlo[(size_t)BH_ * D_ * T_];

// ================= PTX helpers (base-arch only: LDSM/HMMA/LDGSTS) =================
__device__ __forceinline__ uint32_t smem_u32(const void* p) {
    uint32_t a;
    asm("{ .reg .u64 t; cvta.to.shared.u64 t, %1; cvt.u32.u64 %0, t; }" : "=r"(a) : "l"(p));
    return a;
}
__device__ __forceinline__ void ldsm_x4(uint32_t& r0, uint32_t& r1, uint32_t& r2, uint32_t& r3,
                                        uint32_t addr) {
    asm volatile("ldmatrix.sync.aligned.m8n8.x4.shared.b16 {%0,%1,%2,%3}, [%4];"
                 : "=r"(r0), "=r"(r1), "=r"(r2), "=r"(r3) : "r"(addr));
}
__device__ __forceinline__ void mma_bf16(float* d, const uint32_t* a, const uint32_t* b) {
    asm volatile(
        "mma.sync.aligned.m16n8k16.row.col.f32.bf16.bf16.f32 "
        "{%0,%1,%2,%3}, {%4,%5,%6,%7}, {%8,%9}, {%0,%1,%2,%3};"
        : "+f"(d[0]), "+f"(d[1]), "+f"(d[2]), "+f"(d[3])
        : "r"(a[0]), "r"(a[1]), "r"(a[2]), "r"(a[3]), "r"(b[0]), "r"(b[1]));
}
#define CP_ASYNC16(dst, src) \
    asm volatile("cp.async.cg.shared.global [%0], [%1], 16;" :: "r"(dst), "l"(src))
#define CP_COMMIT() asm volatile("cp.async.commit_group;" ::: "memory")
#define CP_WAIT0()  asm volatile("cp.async.wait_group 0;" ::: "memory")

__device__ __forceinline__ uint32_t pack_bf16(float x, float y) {
    __nv_bfloat162 t = __float22bfloat162_rn(make_float2(x, y));
    return *reinterpret_cast<uint32_t*>(&t);
}
__device__ __forceinline__ uint32_t pack_bf16_lo(float x, float y, uint32_t hi) {
    __nv_bfloat162 h = *reinterpret_cast<__nv_bfloat162*>(&hi);
    __nv_bfloat162 t = __float22bfloat162_rn(
        make_float2(x - __bfloat162float(h.x), y - __bfloat162float(h.y)));
    return *reinterpret_cast<uint32_t*>(&t);
}

// ================= fp32 -> bf16 hi/lo split kernel =================
__global__ __launch_bounds__(256) void split_kernel(
    const float* __restrict__ x, __nv_bfloat16* __restrict__ hi,
    __nv_bfloat16* __restrict__ lo, int n8)
{
    int idx = blockIdx.x * blockDim.x + threadIdx.x;
    if (idx >= n8) return;
    float4 v0 = *reinterpret_cast<const float4*>(x + (size_t)idx * 8);
    float4 v1 = *reinterpret_cast<const float4*>(x + (size_t)idx * 8 + 4);
    float v[8] = {v0.x, v0.y, v0.z, v0.w, v1.x, v1.y, v1.z, v1.w};
    __nv_bfloat16 hs[8], ls[8];
    #pragma unroll
    for (int i = 0; i < 8; i++) {
        hs[i] = __float2bfloat16(v[i]);
        ls[i] = __float2bfloat16(v[i] - __bfloat162float(hs[i]));
    }
    *reinterpret_cast<uint4*>(hi + (size_t)idx * 8) = *reinterpret_cast<uint4*>(hs);
    *reinterpret_cast<uint4*>(lo + (size_t)idx * 8) = *reinterpret_cast<uint4*>(ls);
}

// ================= mma.sync GEMM (unchanged from R3) =================
#define BKC      32
#define ROWB     80
#define TILE_B   (128 * ROWB)
#define N_CHUNKS 96

__global__ __launch_bounds__(256) void gemm_mma(
    const __nv_bfloat16* __restrict__ Xhi, const __nv_bfloat16* __restrict__ Xlo,
    const __nv_bfloat16* __restrict__ Whi, const __nv_bfloat16* __restrict__ Wlo,
    const float* __restrict__ bias, float* __restrict__ out,
    float alpha, int split_heads)
{
    __shared__ __align__(16) char sA[2 * TILE_B];
    __shared__ __align__(16) char sB[2 * TILE_B];
    const uint32_t sAb = smem_u32(sA);
    const uint32_t sBb = smem_u32(sB);

    const int tid  = threadIdx.x;
    const int wid  = tid >> 5;
    const int lane = tid & 31;
    const int m0 = blockIdx.y * 128;
    const int n0 = blockIdx.x * 128;
    const int m_w = (wid & 1) * 64;
    const int n_w = (wid >> 1) * 32;

    const int l_row0 = tid >> 2;
    const int l_cs   = (tid & 3);
    const uint32_t l_soff0 = (uint32_t)l_row0 * ROWB + l_cs * 16;
    const uint32_t l_soff1 = (uint32_t)(l_row0 + 64) * ROWB + l_cs * 16;
    const int l_goff = l_cs * 8;

    float acc[4][4][4];
    #pragma unroll
    for (int i = 0; i < 4; i++)
        #pragma unroll
        for (int j = 0; j < 4; j++)
            #pragma unroll
            for (int q = 0; q < 4; q++) acc[i][j][q] = 0.f;

    const uint32_t a_ld_base = (uint32_t)(m_w + (lane & 15)) * ROWB + (lane >> 4) * 16;
    const int bg = lane >> 3;
    const uint32_t b_ld_row = (uint32_t)(n_w + ((bg >> 1) * 8) + (lane & 7)) * ROWB;
    const uint32_t b_ld_col = (uint32_t)(bg & 1) * 16;

    {
        const __nv_bfloat16* sa = Xhi + (size_t)m0 * E_;
        const __nv_bfloat16* sb = Whi + (size_t)n0 * E_;
        CP_ASYNC16(sAb + l_soff0, sa + (size_t)l_row0 * E_ + l_goff);
        CP_ASYNC16(sAb + l_soff1, sa + (size_t)(l_row0 + 64) * E_ + l_goff);
        CP_ASYNC16(sBb + l_soff0, sb + (size_t)l_row0 * E_ + l_goff);
        CP_ASYNC16(sBb + l_soff1, sb + (size_t)(l_row0 + 64) * E_ + l_goff);
        CP_COMMIT();
        CP_WAIT0();
        __syncthreads();
    }

    for (int it = 0; it < N_CHUNKS; ++it) {
        const int buf = it & 1;
        if (it + 1 < N_CHUNKS) {
            const int nit = it + 1;
            const int p  = nit >> 5;
            const int kc = (nit & 31) * BKC;
            const __nv_bfloat16* sa = ((p == 2) ? Xlo : Xhi) + (size_t)m0 * E_ + kc;
            const __nv_bfloat16* sb = ((p == 1) ? Wlo : Whi) + (size_t)n0 * E_ + kc;
            const uint32_t ab = sAb + (buf ^ 1) * TILE_B;
            const uint32_t bb = sBb + (buf ^ 1) * TILE_B;
            CP_ASYNC16(ab + l_soff0, sa + (size_t)l_row0 * E_ + l_goff);
            CP_ASYNC16(ab + l_soff1, sa + (size_t)(l_row0 + 64) * E_ + l_goff);
            CP_ASYNC16(bb + l_soff0, sb + (size_t)l_row0 * E_ + l_goff);
            CP_ASYNC16(bb + l_soff1, sb + (size_t)(l_row0 + 64) * E_ + l_goff);
            CP_COMMIT();
        }

        const uint32_t at = sAb + buf * TILE_B;
        const uint32_t bt = sBb + buf * TILE_B;
        #pragma unroll
        for (int ks = 0; ks < 2; ks++) {
            uint32_t af[4][4];
            #pragma unroll
            for (int mf = 0; mf < 4; mf++)
                ldsm_x4(af[mf][0], af[mf][1], af[mf][2], af[mf][3],
                        at + a_ld_base + (uint32_t)mf * 16 * ROWB + ks * 32);
            uint32_t bf[4][2];
            #pragma unroll
            for (int nf2 = 0; nf2 < 2; nf2++) {
                uint32_t r0, r1, r2, r3;
                ldsm_x4(r0, r1, r2, r3,
                        bt + b_ld_row + (uint32_t)nf2 * 16 * ROWB + b_ld_col + ks * 32);
                bf[nf2 * 2 + 0][0] = r0; bf[nf2 * 2 + 0][1] = r1;
                bf[nf2 * 2 + 1][0] = r2; bf[nf2 * 2 + 1][1] = r3;
            }
            #pragma unroll
            for (int mf = 0; mf < 4; mf++)
                #pragma unroll
                for (int nf = 0; nf < 4; nf++)
                    mma_bf16(acc[mf][nf], af[mf], bf[nf]);
        }

        CP_WAIT0();
        __syncthreads();
    }

    #pragma unroll
    for (int mf = 0; mf < 4; mf++) {
        #pragma unroll
        for (int half = 0; half < 2; half++) {
            const int m = m0 + m_w + mf * 16 + (lane >> 2) + half * 8;
            const int bb = m >> 10;
            const int t  = m & 1023;
            #pragma unroll
            for (int nf = 0; nf < 4; nf++) {
                const int n = n0 + n_w + nf * 8 + (lane & 3) * 2;
                float2 v;
                v.x = (acc[mf][nf][half * 2 + 0] + __ldg(bias + n)) * alpha;
                v.y = (acc[mf][nf][half * 2 + 1] + __ldg(bias + n + 1)) * alpha;
                if (split_heads) {
                    const int h = n >> 6, d = n & 63;
                    *reinterpret_cast<float2*>(
                        out + (((size_t)(bb * H_ + h)) * T_ + t) * D_ + d) = v;
                } else {
                    *reinterpret_cast<float2*>(out + (size_t)m * E_ + n) = v;
                }
            }
        }
    }
}

// ---------------- XPos rotary + bf16 hi/lo split (Q and K) ----------------
__global__ __launch_bounds__(256) void xpos_split_kernel()
{
    int idx = blockIdx.x * blockDim.x + threadIdx.x;
    if (idx >= BH_ * T_ * (D_ / 2)) return;
    int j  = idx & 31;
    int t  = (idx >> 5) & 1023;
    int bh = idx >> 15;

    float sj    = (2.f * j + 0.4f * (float)D_) / (1.4f * (float)D_);
    float pos   = (float)t - (float)(T_ / 2);
    float scale = powf(sj, pos * (1.f / (float)E_));
    float invf  = powf(10000.f, -(float)j / 32.f);
    float sn, cs;
    sincosf((float)t * invf, &sn, &cs);

    size_t base = ((size_t)bh * T_ + t) * D_ + 2 * j;

    // q: upscale
    {
        float cq = cs * scale, sq = sn * scale;
        float x1 = g_Q[base], x2 = g_Q[base + 1];
        float y1 = x1 * cq - x2 * sq;
        float y2 = x2 * cq + x1 * sq;
        __nv_bfloat162 hi, lo;
        hi.x = __float2bfloat16(y1); hi.y = __float2bfloat16(y2);
        lo.x = __float2bfloat16(y1 - __bfloat162float(hi.x));
        lo.y = __float2bfloat16(y2 - __bfloat162float(hi.y));
        *reinterpret_cast<__nv_bfloat162*>(g_Qhi + base) = hi;
        *reinterpret_cast<__nv_bfloat162*>(g_Qlo + base) = lo;
    }
    // k: downscale
    {
        float inv = 1.f / scale;
        float ck = cs * inv, sk = sn * inv;
        float x1 = g_K[base], x2 = g_K[base + 1];
        float y1 = x1 * ck - x2 * sk;
        float y2 = x2 * ck + x1 * sk;
        __nv_bfloat162 hi, lo;
        hi.x = __float2bfloat16(y1); hi.y = __float2bfloat16(y2);
        lo.x = __float2bfloat16(y1 - __bfloat162float(hi.x));
        lo.y = __float2bfloat16(y2 - __bfloat162float(hi.y));
        *reinterpret_cast<__nv_bfloat162*>(g_Khi + base) = hi;
        *reinterpret_cast<__nv_bfloat162*>(g_Klo + base) = lo;
    }
}

// ---------------- V transpose + split: g_V [bh,t,d] -> Vt [bh,d,s] ----------------
__global__ __launch_bounds__(256) void vt_split_kernel()
{
    __shared__ float ts[64][65];
    const int bh = blockIdx.x;
    const int s0 = blockIdx.y * 64;
    const int tid = threadIdx.x;

    #pragma unroll
    for (int i = 0; i < 16; i++) {
        int idx = tid + i * 256;
        int r = idx >> 6, d = idx & 63;
        ts[r][d] = g_V[((size_t)bh * T_ + s0 + r) * D_ + d];
    }
    __syncthreads();
    #pragma unroll
    for (int i = 0; i < 16; i++) {
        int idx = tid + i * 256;
        int d = idx >> 6, r = idx & 63;
        float v = ts[r][d];
        __nv_bfloat16 hi = __float2bfloat16(v);
        __nv_bfloat16 lo = __float2bfloat16(v - __bfloat162float(hi));
        size_t o = ((size_t)bh * D_ + d) * T_ + s0 + r;
        g_Vthi[o] = hi;
        g_Vtlo[o] = lo;
    }
}

// ================= Flash attention on mma.sync (bf16 3-term split) =================
// block = (bh, 64 q-rows); 4 warps x 16 q-rows. s-tiles of 64.
// smem: 6 tiles of 64x64 bf16, 128B rows, XOR-swizzled (seg ^= row&7).
#define SQHI 0
#define SQLO 8192
#define SKHI 16384
#define SKLO 24576
#define SVHI 32768
#define SVLO 40960

__global__ __launch_bounds__(128) void attn_mma()
{
    __shared__ __align__(128) char smem[49152];
    const uint32_t sb = smem_u32(smem);
    const int tid  = threadIdx.x;
    const int wid  = tid >> 5;
    const int lane = tid & 31;
    const int bh = blockIdx.x;
    const int qt = blockIdx.y;

    // ---- load Q tiles (once) ----
    {
        const __nv_bfloat16* qh = g_Qhi + ((size_t)bh * T_ + qt * 64) * D_;
        const __nv_bfloat16* ql = g_Qlo + ((size_t)bh * T_ + qt * 64) * D_;
        #pragma unroll
        for (int i = 0; i < 4; i++) {
            int idx = tid + i * 128;
            int row = idx >> 3, seg = idx & 7;
            uint32_t off = (uint32_t)row * 128 + ((seg ^ (row & 7)) * 16);
            CP_ASYNC16(sb + SQHI + off, qh + (size_t)row * D_ + seg * 8);
            CP_ASYNC16(sb + SQLO + off, ql + (size_t)row * D_ + seg * 8);
        }
        CP_COMMIT(); CP_WAIT0();
        __syncthreads();
    }

    // ---- Q fragments (persistent) ----
    uint32_t qh[4][4], ql[4][4];
    {
        const int row = wid * 16 + (lane & 15);
        const uint32_t rb = (uint32_t)row * 128;
        #pragma unroll
        for (int ks = 0; ks < 4; ks++) {
            int seg = ks * 2 + (lane >> 4);
            uint32_t off = rb + ((seg ^ (row & 7)) * 16);
            ldsm_x4(qh[ks][0], qh[ks][1], qh[ks][2], qh[ks][3], sb + SQHI + off);
            ldsm_x4(ql[ks][0], ql[ks][1], ql[ks][2], ql[ks][3], sb + SQLO + off);
        }
    }

    float m0 = -1e30f, m1 = -1e30f, l0 = 0.f, l1 = 0.f;
    float o[8][4];
    #pragma unroll
    for (int nf = 0; nf < 8; nf++)
        #pragma unroll
        for (int q = 0; q < 4; q++) o[nf][q] = 0.f;

    // B-frag address components (shared for K and Vt tiles)
    const int bg = lane >> 3;
    const int brow_lo = ((bg >> 1) * 8) + (lane & 7);
    const int bseg0 = bg & 1;

    for (int st = 0; st < 16; st++) {
        // ---- load K/V tiles ----
        if (st > 0) __syncthreads();
        {
            const int s0 = st * 64;
            const __nv_bfloat16* kh = g_Khi + ((size_t)bh * T_ + s0) * D_;
            const __nv_bfloat16* kl = g_Klo + ((size_t)bh * T_ + s0) * D_;
            const __nv_bfloat16* vh = g_Vthi + (size_t)bh * D_ * T_ + s0;
            const __nv_bfloat16* vl = g_Vtlo + (size_t)bh * D_ * T_ + s0;
            #pragma unroll
            for (int i = 0; i < 4; i++) {
                int idx = tid + i * 128;
                int row = idx >> 3, seg = idx & 7;
                uint32_t off = (uint32_t)row * 128 + ((seg ^ (row & 7)) * 16);
                CP_ASYNC16(sb + SKHI + off, kh + (size_t)row * D_ + seg * 8);
                CP_ASYNC16(sb + SKLO + off, kl + (size_t)row * D_ + seg * 8);
                CP_ASYNC16(sb + SVHI + off, vh + (size_t)row * T_ + seg * 8);
                CP_ASYNC16(sb + SVLO + off, vl + (size_t)row * T_ + seg * 8);
            }
            CP_COMMIT(); CP_WAIT0();
            __syncthreads();
        }

        // ---- S = Qhi Khi^T + Qhi Klo^T + Qlo Khi^T ----
        float sacc[8][4];
        #pragma unroll
        for (int nf = 0; nf < 8; nf++)
            #pragma unroll
            for (int q = 0; q < 4; q++) sacc[nf][q] = 0.f;

        #pragma unroll
        for (int ph = 0; ph < 3; ph++) {
            const uint32_t (*aq)[4] = (ph == 2) ? ql : qh;
            const uint32_t kt = sb + ((ph == 1) ? SKLO : SKHI);
            #pragma unroll
            for (int ks = 0; ks < 4; ks++) {
                uint32_t bf[8][2];
                #pragma unroll
                for (int nf2 = 0; nf2 < 4; nf2++) {
                    int row = nf2 * 16 + brow_lo;
                    int seg = (ks * 2 + bseg0) ^ (row & 7);
                    uint32_t r0, r1, r2, r3;
                    ldsm_x4(r0, r1, r2, r3, kt + (uint32_t)row * 128 + seg * 16);
                    bf[nf2 * 2 + 0][0] = r0; bf[nf2 * 2 + 0][1] = r1;
                    bf[nf2 * 2 + 1][0] = r2; bf[nf2 * 2 + 1][1] = r3;
                }
                #pragma unroll
                for (int nf = 0; nf < 8; nf++)
                    mma_bf16(sacc[nf], aq[ks], bf[nf]);
            }
        }

        // ---- online softmax ----
        float mx0 = m0, mx1 = m1;
        #pragma unroll
        for (int nf = 0; nf < 8; nf++) {
            mx0 = fmaxf(mx0, fmaxf(sacc[nf][0], sacc[nf][1]));
            mx1 = fmaxf(mx1, fmaxf(sacc[nf][2], sacc[nf][3]));
        }
        mx0 = fmaxf(mx0, __shfl_xor_sync(0xffffffffu, mx0, 1));
        mx0 = fmaxf(mx0, __shfl_xor_sync(0xffffffffu, mx0, 2));
        mx1 = fmaxf(mx1, __shfl_xor_sync(0xffffffffu, mx1, 1));
        mx1 = fmaxf(mx1, __shfl_xor_sync(0xffffffffu, mx1, 2));

        const float c0 = __expf(m0 - mx0);
        const float c1 = __expf(m1 - mx1);
        m0 = mx0; m1 = mx1;
        l0 *= c0; l1 *= c1;
        #pragma unroll
        for (int nf = 0; nf < 8; nf++) {
            o[nf][0] *= c0; o[nf][1] *= c0;
            o[nf][2] *= c1; o[nf][3] *= c1;
        }
        #pragma unroll
        for (int nf = 0; nf < 8; nf++) {
            float e0 = __expf(sacc[nf][0] - m0);
            float e1 = __expf(sacc[nf][1] - m0);
            float e2 = __expf(sacc[nf][2] - m1);
            float e3 = __expf(sacc[nf][3] - m1);
            l0 += e0 + e1; l1 += e2 + e3;
            sacc[nf][0] = e0; sacc[nf][1] = e1;
            sacc[nf][2] = e2; sacc[nf][3] = e3;
        }

        // ---- P -> bf16 hi/lo A-fragments ----
        uint32_t phi[4][4], plo[4][4];
        #pragma unroll
        for (int ks = 0; ks < 4; ks++) {
            phi[ks][0] = pack_bf16(sacc[2 * ks][0],     sacc[2 * ks][1]);
            phi[ks][1] = pack_bf16(sacc[2 * ks][2],     sacc[2 * ks][3]);
            phi[ks][2] = pack_bf16(sacc[2 * ks + 1][0], sacc[2 * ks + 1][1]);
            phi[ks][3] = pack_bf16(sacc[2 * ks + 1][2], sacc[2 * ks + 1][3]);
            plo[ks][0] = pack_bf16_lo(sacc[2 * ks][0],     sacc[2 * ks][1],     phi[ks][0]);
            plo[ks][1] = pack_bf16_lo(sacc[2 * ks][2],     sacc[2 * ks][3],     phi[ks][1]);
            plo[ks][2] = pack_bf16_lo(sacc[2 * ks + 1][0], sacc[2 * ks + 1][1], phi[ks][2]);
            plo[ks][3] = pack_bf16_lo(sacc[2 * ks + 1][2], sacc[2 * ks + 1][3], phi[ks][3]);
        }

        // ---- O += Phi Vhi + Phi Vlo + Plo Vhi ----
        #pragma unroll
        for (int ph = 0; ph < 3; ph++) {
            const uint32_t (*ap)[4] = (ph == 2) ? plo : phi;
            const uint32_t vt = sb + ((ph == 1) ? SVLO : SVHI);
            #pragma unroll
            for (int ks = 0; ks < 4; ks++) {
                uint32_t bf[8][2];
                #pragma unroll
                for (int nf2 = 0; nf2 < 4; nf2++) {
                    int row = nf2 * 16 + brow_lo;   // row = d
                    int seg = (ks * 2 + bseg0) ^ (row & 7);
                    uint32_t r0, r1, r2, r3;
                    ldsm_x4(r0, r1, r2, r3, vt + (uint32_t)row * 128 + seg * 16);
                    bf[nf2 * 2 + 0][0] = r0; bf[nf2 * 2 + 0][1] = r1;
                    bf[nf2 * 2 + 1][0] = r2; bf[nf2 * 2 + 1][1] = r3;
                }
                #pragma unroll
                for (int nf = 0; nf < 8; nf++)
                    mma_bf16(o[nf], ap[ks], bf[nf]);
            }
        }
    }

    // ---- finalize ----
    l0 += __shfl_xor_sync(0xffffffffu, l0, 1);
    l0 += __shfl_xor_sync(0xffffffffu, l0, 2);
    l1 += __shfl_xor_sync(0xffffffffu, l1, 1);
    l1 += __shfl_xor_sync(0xffffffffu, l1, 2);
    const float inv0 = 1.f / l0;
    const float inv1 = 1.f / l1;

    const int t0 = qt * 64 + wid * 16 + (lane >> 2);
    const int b = bh >> 4, h = bh & 15;
    float* base0 = g_C + ((size_t)(b * T_ + t0)) * E_ + h * D_ + (lane & 3) * 2;
    float* base1 = base0 + (size_t)8 * E_;
    #pragma unroll
    for (int nf = 0; nf < 8; nf++) {
        float2 v0 = make_float2(o[nf][0] * inv0, o[nf][1] * inv0);
        float2 v1 = make_float2(o[nf][2] * inv1, o[nf][3] * inv1);
        *reinterpret_cast<float2*>(base0 + nf * 8) = v0;
        *reinterpret_cast<float2*>(base1 + nf * 8) = v1;
    }
}

// ---------------- launch ----------------
extern "C" void kernel_launch(void* const* d_in, const int* in_sizes, int n_in,
                              void* d_out, int out_size)
{
    const float* query = (const float*)d_in[0];
    const float* key   = (const float*)d_in[1];
    const float* value = (const float*)d_in[2];
    const float* wq    = (const float*)d_in[3];
    const float* bq    = (const float*)d_in[4];
    const float* wk    = (const float*)d_in[5];
    const float* bk    = (const float*)d_in[6];
    const float* wv    = (const float*)d_in[7];
    const float* bv    = (const float*)d_in[8];
    const float* wo    = (const float*)d_in[9];
    const float* bo    = (const float*)d_in[10];
    float* out = (float*)d_out;

    float *Q, *K, *V, *C;
    cudaGetSymbolAddress((void**)&Q, g_Q);
    cudaGetSymbolAddress((void**)&K, g_K);
    cudaGetSymbolAddress((void**)&V, g_V);
    cudaGetSymbolAddress((void**)&C, g_C);
    __nv_bfloat16 *Xhi, *Xlo, *Whi, *Wlo;
    cudaGetSymbolAddress((void**)&Xhi, g_Xhi);
    cudaGetSymbolAddress((void**)&Xlo, g_Xlo);
    cudaGetSymbolAddress((void**)&Whi, g_Whi);
    cudaGetSymbolAddress((void**)&Wlo, g_Wlo);

    dim3 gemm_grid(E_ / 128, M_ / 128);
    const int actn8 = (M_ * E_) / 8;
    const int wn8   = (E_ * E_) / 8;
    const float scaling = 0.125f;

    split_kernel<<<actn8 / 256, 256>>>(query, Xhi, Xlo, actn8);
    split_kernel<<<wn8 / 256, 256>>>(wq, Whi, Wlo, wn8);
    gemm_mma<<<gemm_grid, 256>>>(Xhi, Xlo, Whi, Wlo, bq, Q, scaling, 1);

    split_kernel<<<actn8 / 256, 256>>>(key, Xhi, Xlo, actn8);
    split_kernel<<<wn8 / 256, 256>>>(wk, Whi, Wlo, wn8);
    gemm_mma<<<gemm_grid, 256>>>(Xhi, Xlo, Whi, Wlo, bk, K, 1.f, 1);

    split_kernel<<<actn8 / 256, 256>>>(value, Xhi, Xlo, actn8);
    split_kernel<<<wn8 / 256, 256>>>(wv, Whi, Wlo, wn8);
    gemm_mma<<<gemm_grid, 256>>>(Xhi, Xlo, Whi, Wlo, bv, V, 1.f, 1);

    int xpos_threads = BH_ * T_ * (D_ / 2);
    xpos_split_kernel<<<xpos_threads / 256, 256>>>();
    vt_split_kernel<<<dim3(BH_, T_ / 64), 256>>>();

    attn_mma<<<dim3(BH_, T_ / 64), 128>>>();

    split_kernel<<<actn8 / 256, 256>>>(C, Xhi, Xlo, actn8);
    split_kernel<<<wn8 / 256, 256>>>(wo, Whi, Wlo, wn8);
    gemm_mma<<<gemm_grid, 256>>>(Xhi, Xlo, Whi, Wlo, bo, out, 1.f, 0);
}

// round 5
// speedup vs baseline: 2.9538x; 1.0629x over previous
#include <cuda_runtime.h>
#include <cuda_bf16.h>
#include <math.h>
#include <cstdint>

#define B_   8
#define T_   1024
#define E_   1024
#define H_   16
#define D_   64
#define BH_  (B_*H_)   /* 128 */
#define M_   (B_*T_)   /* 8192 */

// ---------------- device scratch (no allocations allowed) ----------------
__device__ float g_Q[(size_t)BH_ * T_ * D_];   // fp32 head-split [bh, t, d]
__device__ float g_K[(size_t)BH_ * T_ * D_];
__device__ float g_V[(size_t)BH_ * T_ * D_];
__device__ float g_C[(size_t)M_ * E_];         // merged context [b*t, e]

// packed split buffers: z-th slice for z in {q,k,v}
__device__ __align__(256) __nv_bfloat16 g_Xhi3[(size_t)3 * M_ * E_];
__device__ __align__(256) __nv_bfloat16 g_Xlo3[(size_t)3 * M_ * E_];
__device__ __align__(256) __nv_bfloat16 g_Whi3[(size_t)3 * E_ * E_];
__device__ __align__(256) __nv_bfloat16 g_Wlo3[(size_t)3 * E_ * E_];

// attention bf16 operands (post-xpos), head-split
__device__ __align__(256) __nv_bfloat16 g_Qhi[(size_t)BH_ * T_ * D_];
__device__ __align__(256) __nv_bfloat16 g_Qlo[(size_t)BH_ * T_ * D_];
__device__ __align__(256) __nv_bfloat16 g_Khi[(size_t)BH_ * T_ * D_];
__device__ __align__(256) __nv_bfloat16 g_Klo[(size_t)BH_ * T_ * D_];
__device__ __align__(256) __nv_bfloat16 g_Vthi[(size_t)BH_ * D_ * T_];  // [bh, d, s]
__device__ __align__(256) __nv_bfloat16 g_Vtlo[(size_t)BH_ * D_ * T_];

// ================= PTX helpers (base-arch only: LDSM/HMMA/LDGSTS) =================
__device__ __forceinline__ uint32_t smem_u32(const void* p) {
    uint32_t a;
    asm("{ .reg .u64 t; cvta.to.shared.u64 t, %1; cvt.u32.u64 %0, t; }" : "=r"(a) : "l"(p));
    return a;
}
__device__ __forceinline__ void ldsm_x4(uint32_t& r0, uint32_t& r1, uint32_t& r2, uint32_t& r3,
                                        uint32_t addr) {
    asm volatile("ldmatrix.sync.aligned.m8n8.x4.shared.b16 {%0,%1,%2,%3}, [%4];"
                 : "=r"(r0), "=r"(r1), "=r"(r2), "=r"(r3) : "r"(addr));
}
__device__ __forceinline__ void mma_bf16(float* d, const uint32_t* a, const uint32_t* b) {
    asm volatile(
        "mma.sync.aligned.m16n8k16.row.col.f32.bf16.bf16.f32 "
        "{%0,%1,%2,%3}, {%4,%5,%6,%7}, {%8,%9}, {%0,%1,%2,%3};"
        : "+f"(d[0]), "+f"(d[1]), "+f"(d[2]), "+f"(d[3])
        : "r"(a[0]), "r"(a[1]), "r"(a[2]), "r"(a[3]), "r"(b[0]), "r"(b[1]));
}
#define CP_ASYNC16(dst, src) \
    asm volatile("cp.async.cg.shared.global [%0], [%1], 16;" :: "r"(dst), "l"(src))
#define CP_COMMIT() asm volatile("cp.async.commit_group;" ::: "memory")
#define CP_WAIT0()  asm volatile("cp.async.wait_group 0;" ::: "memory")
#define CP_WAIT1()  asm volatile("cp.async.wait_group 1;" ::: "memory")

__device__ __forceinline__ uint32_t pack_bf16(float x, float y) {
    __nv_bfloat162 t = __float22bfloat162_rn(make_float2(x, y));
    return *reinterpret_cast<uint32_t*>(&t);
}
__device__ __forceinline__ uint32_t pack_bf16_lo(float x, float y, uint32_t hi) {
    __nv_bfloat162 h = *reinterpret_cast<__nv_bfloat162*>(&hi);
    __nv_bfloat162 t = __float22bfloat162_rn(
        make_float2(x - __bfloat162float(h.x), y - __bfloat162float(h.y)));
    return *reinterpret_cast<uint32_t*>(&t);
}

// ================= fp32 -> bf16 hi/lo split kernel =================
__global__ __launch_bounds__(256) void split_kernel(
    const float* __restrict__ x, __nv_bfloat16* __restrict__ hi,
    __nv_bfloat16* __restrict__ lo, int n8)
{
    int idx = blockIdx.x * blockDim.x + threadIdx.x;
    if (idx >= n8) return;
    float4 v0 = *reinterpret_cast<const float4*>(x + (size_t)idx * 8);
    float4 v1 = *reinterpret_cast<const float4*>(x + (size_t)idx * 8 + 4);
    float v[8] = {v0.x, v0.y, v0.z, v0.w, v1.x, v1.y, v1.z, v1.w};
    __nv_bfloat16 hs[8], ls[8];
    #pragma unroll
    for (int i = 0; i < 8; i++) {
        hs[i] = __float2bfloat16(v[i]);
        ls[i] = __float2bfloat16(v[i] - __bfloat162float(hs[i]));
    }
    *reinterpret_cast<uint4*>(hi + (size_t)idx * 8) = *reinterpret_cast<uint4*>(hs);
    *reinterpret_cast<uint4*>(lo + (size_t)idx * 8) = *reinterpret_cast<uint4*>(ls);
}

// ================= 3-stage pipelined mma.sync GEMM body =================
// out = (X @ W^T + bias) * alpha, K' = 3*1024 phases, tile 128x128, BK=32.
#define BKC      32
#define ROWB     80
#define TILE_B   (128 * ROWB)     /* 10240 B */
#define STAGE_B  (2 * TILE_B)     /* A+B per stage */
#define GEMM_SMEM (3 * STAGE_B)   /* 61440 B */
#define N_CHUNKS 96

__device__ __forceinline__ void gemm_body(
    char* smem,
    const __nv_bfloat16* __restrict__ Xhi, const __nv_bfloat16* __restrict__ Xlo,
    const __nv_bfloat16* __restrict__ Whi, const __nv_bfloat16* __restrict__ Wlo,
    const float* __restrict__ bias, float* __restrict__ out,
    float alpha, int split_heads, int m0, int n0)
{
    const uint32_t sbase = smem_u32(smem);
    const int tid  = threadIdx.x;
    const int wid  = tid >> 5;
    const int lane = tid & 31;
    const int m_w = (wid & 1) * 64;
    const int n_w = (wid >> 1) * 32;

    const int l_row0 = tid >> 2;
    const int l_cs   = (tid & 3);
    const uint32_t l_soff0 = (uint32_t)l_row0 * ROWB + l_cs * 16;
    const uint32_t l_soff1 = (uint32_t)(l_row0 + 64) * ROWB + l_cs * 16;
    const int l_goff = l_cs * 8;

    float acc[4][4][4];
    #pragma unroll
    for (int i = 0; i < 4; i++)
        #pragma unroll
        for (int j = 0; j < 4; j++)
            #pragma unroll
            for (int q = 0; q < 4; q++) acc[i][j][q] = 0.f;

    const uint32_t a_ld_base = (uint32_t)(m_w + (lane & 15)) * ROWB + (lane >> 4) * 16;
    const int bg = lane >> 3;
    const uint32_t b_ld_row = (uint32_t)(n_w + ((bg >> 1) * 8) + (lane & 7)) * ROWB;
    const uint32_t b_ld_col = (uint32_t)(bg & 1) * 16;

    // issue loads for chunk c into stage s
    auto issue = [&](int c, int s) {
        const int p  = c >> 5;
        const int kc = (c & 31) * BKC;
        const __nv_bfloat16* sa = ((p == 2) ? Xlo : Xhi) + (size_t)m0 * E_ + kc;
        const __nv_bfloat16* sw = ((p == 1) ? Wlo : Whi) + (size_t)n0 * E_ + kc;
        const uint32_t ab = sbase + (uint32_t)s * STAGE_B;
        const uint32_t bb = ab + TILE_B;
        CP_ASYNC16(ab + l_soff0, sa + (size_t)l_row0 * E_ + l_goff);
        CP_ASYNC16(ab + l_soff1, sa + (size_t)(l_row0 + 64) * E_ + l_goff);
        CP_ASYNC16(bb + l_soff0, sw + (size_t)l_row0 * E_ + l_goff);
        CP_ASYNC16(bb + l_soff1, sw + (size_t)(l_row0 + 64) * E_ + l_goff);
    };

    // prologue: chunks 0,1 into stages 0,1
    issue(0, 0); CP_COMMIT();
    issue(1, 1); CP_COMMIT();

    int s_cur = 0;   // stage of chunk `it`
    for (int it = 0; it < N_CHUNKS; ++it) {
        CP_WAIT1();          // chunk `it` resident (this thread)
        __syncthreads();     // visible to all; all warps done with stage s_nxt's old data

        // stage to fill = the one after next = (s_cur+2)%3
        int s_fill = s_cur + 2; if (s_fill >= 3) s_fill -= 3;
        if (it + 2 < N_CHUNKS) issue(it + 2, s_fill);
        CP_COMMIT();         // always commit (possibly empty) to keep counts uniform

        const uint32_t at = sbase + (uint32_t)s_cur * STAGE_B;
        const uint32_t bt = at + TILE_B;
        #pragma unroll
        for (int ks = 0; ks < 2; ks++) {
            uint32_t af[4][4];
            #pragma unroll
            for (int mf = 0; mf < 4; mf++)
                ldsm_x4(af[mf][0], af[mf][1], af[mf][2], af[mf][3],
                        at + a_ld_base + (uint32_t)mf * 16 * ROWB + ks * 32);
            uint32_t bf[4][2];
            #pragma unroll
            for (int nf2 = 0; nf2 < 2; nf2++) {
                uint32_t r0, r1, r2, r3;
                ldsm_x4(r0, r1, r2, r3,
                        bt + b_ld_row + (uint32_t)nf2 * 16 * ROWB + b_ld_col + ks * 32);
                bf[nf2 * 2 + 0][0] = r0; bf[nf2 * 2 + 0][1] = r1;
                bf[nf2 * 2 + 1][0] = r2; bf[nf2 * 2 + 1][1] = r3;
            }
            #pragma unroll
            for (int mf = 0; mf < 4; mf++)
                #pragma unroll
                for (int nf = 0; nf < 4; nf++)
                    mma_bf16(acc[mf][nf], af[mf], bf[nf]);
        }

        if (++s_cur >= 3) s_cur = 0;
    }

    #pragma unroll
    for (int mf = 0; mf < 4; mf++) {
        #pragma unroll
        for (int half = 0; half < 2; half++) {
            const int m = m0 + m_w + mf * 16 + (lane >> 2) + half * 8;
            const int bb = m >> 10;
            const int t  = m & 1023;
            #pragma unroll
            for (int nf = 0; nf < 4; nf++) {
                const int n = n0 + n_w + nf * 8 + (lane & 3) * 2;
                float2 v;
                v.x = (acc[mf][nf][half * 2 + 0] + __ldg(bias + n)) * alpha;
                v.y = (acc[mf][nf][half * 2 + 1] + __ldg(bias + n + 1)) * alpha;
                if (split_heads) {
                    const int h = n >> 6, d = n & 63;
                    *reinterpret_cast<float2*>(
                        out + (((size_t)(bb * H_ + h)) * T_ + t) * D_ + d) = v;
                } else {
                    *reinterpret_cast<float2*>(out + (size_t)m * E_ + n) = v;
                }
            }
        }
    }
}

// merged QKV projection: z selects {q,k,v}
__global__ __launch_bounds__(256, 2) void gemm_qkv(
    const float* __restrict__ bq, const float* __restrict__ bk, const float* __restrict__ bv,
    float* __restrict__ Q, float* __restrict__ K, float* __restrict__ V)
{
    extern __shared__ char smem[];
    const int z = blockIdx.z;
    const size_t xo = (size_t)z * M_ * E_;
    const size_t wo = (size_t)z * E_ * E_;
    const float* bias = (z == 0) ? bq : (z == 1) ? bk : bv;
    float* out = (z == 0) ? Q : (z == 1) ? K : V;
    const float alpha = (z == 0) ? 0.125f : 1.f;
    gemm_body(smem, g_Xhi3 + xo, g_Xlo3 + xo, g_Whi3 + wo, g_Wlo3 + wo,
              bias, out, alpha, 1, blockIdx.y * 128, blockIdx.x * 128);
}

// output projection
__global__ __launch_bounds__(256, 2) void gemm_out(
    const float* __restrict__ bias, float* __restrict__ out)
{
    extern __shared__ char smem[];
    gemm_body(smem, g_Xhi3, g_Xlo3, g_Whi3, g_Wlo3,
              bias, out, 1.f, 0, blockIdx.y * 128, blockIdx.x * 128);
}

// ---------------- XPos rotary + bf16 hi/lo split (Q and K) ----------------
__global__ __launch_bounds__(256) void xpos_split_kernel()
{
    int idx = blockIdx.x * blockDim.x + threadIdx.x;
    if (idx >= BH_ * T_ * (D_ / 2)) return;
    int j  = idx & 31;
    int t  = (idx >> 5) & 1023;
    int bh = idx >> 15;

    float sj    = (2.f * j + 0.4f * (float)D_) / (1.4f * (float)D_);
    float pos   = (float)t - (float)(T_ / 2);
    float scale = powf(sj, pos * (1.f / (float)E_));
    float invf  = powf(10000.f, -(float)j / 32.f);
    float sn, cs;
    sincosf((float)t * invf, &sn, &cs);

    size_t base = ((size_t)bh * T_ + t) * D_ + 2 * j;

    {
        float cq = cs * scale, sq = sn * scale;
        float x1 = g_Q[base], x2 = g_Q[base + 1];
        float y1 = x1 * cq - x2 * sq;
        float y2 = x2 * cq + x1 * sq;
        __nv_bfloat162 hi, lo;
        hi.x = __float2bfloat16(y1); hi.y = __float2bfloat16(y2);
        lo.x = __float2bfloat16(y1 - __bfloat162float(hi.x));
        lo.y = __float2bfloat16(y2 - __bfloat162float(hi.y));
        *reinterpret_cast<__nv_bfloat162*>(g_Qhi + base) = hi;
        *reinterpret_cast<__nv_bfloat162*>(g_Qlo + base) = lo;
    }
    {
        float inv = 1.f / scale;
        float ck = cs * inv, sk = sn * inv;
        float x1 = g_K[base], x2 = g_K[base + 1];
        float y1 = x1 * ck - x2 * sk;
        float y2 = x2 * ck + x1 * sk;
        __nv_bfloat162 hi, lo;
        hi.x = __float2bfloat16(y1); hi.y = __float2bfloat16(y2);
        lo.x = __float2bfloat16(y1 - __bfloat162float(hi.x));
        lo.y = __float2bfloat16(y2 - __bfloat162float(hi.y));
        *reinterpret_cast<__nv_bfloat162*>(g_Khi + base) = hi;
        *reinterpret_cast<__nv_bfloat162*>(g_Klo + base) = lo;
    }
}

// ---------------- V transpose + split ----------------
__global__ __launch_bounds__(256) void vt_split_kernel()
{
    __shared__ float ts[64][65];
    const int bh = blockIdx.x;
    const int s0 = blockIdx.y * 64;
    const int tid = threadIdx.x;

    #pragma unroll
    for (int i = 0; i < 16; i++) {
        int idx = tid + i * 256;
        int r = idx >> 6, d = idx & 63;
        ts[r][d] = g_V[((size_t)bh * T_ + s0 + r) * D_ + d];
    }
    __syncthreads();
    #pragma unroll
    for (int i = 0; i < 16; i++) {
        int idx = tid + i * 256;
        int d = idx >> 6, r = idx & 63;
        float v = ts[r][d];
        __nv_bfloat16 hi = __float2bfloat16(v);
        __nv_bfloat16 lo = __float2bfloat16(v - __bfloat162float(hi));
        size_t o = ((size_t)bh * D_ + d) * T_ + s0 + r;
        g_Vthi[o] = hi;
        g_Vtlo[o] = lo;
    }
}

// ================= Flash attention on mma.sync, double-buffered KV =================
// dynamic smem: Q hi/lo 2x8KB at 0/8192; stage s at 16384 + s*32768:
//   KHI +0, KLO +8192, VHI +16384, VLO +24576.   total 81920 B
#define ASM_Q    0
#define ASM_ST0  16384
#define ASM_STS  32768
#define ATTN_SMEM 81920

__global__ __launch_bounds__(128) void attn_mma()
{
    extern __shared__ char smem[];
    const uint32_t sb = smem_u32(smem);
    const int tid  = threadIdx.x;
    const int wid  = tid >> 5;
    const int lane = tid & 31;
    const int bh = blockIdx.x;
    const int qt = blockIdx.y;

    auto issue_kv = [&](int st, int s) {
        const int s0 = st * 64;
        const uint32_t base = sb + ASM_ST0 + (uint32_t)s * ASM_STS;
        const __nv_bfloat16* kh = g_Khi + ((size_t)bh * T_ + s0) * D_;
        const __nv_bfloat16* kl = g_Klo + ((size_t)bh * T_ + s0) * D_;
        const __nv_bfloat16* vh = g_Vthi + (size_t)bh * D_ * T_ + s0;
        const __nv_bfloat16* vl = g_Vtlo + (size_t)bh * D_ * T_ + s0;
        #pragma unroll
        for (int i = 0; i < 4; i++) {
            int idx = tid + i * 128;
            int row = idx >> 3, seg = idx & 7;
            uint32_t off = (uint32_t)row * 128 + ((seg ^ (row & 7)) * 16);
            CP_ASYNC16(base + off,         kh + (size_t)row * D_ + seg * 8);
            CP_ASYNC16(base + 8192 + off,  kl + (size_t)row * D_ + seg * 8);
            CP_ASYNC16(base + 16384 + off, vh + (size_t)row * T_ + seg * 8);
            CP_ASYNC16(base + 24576 + off, vl + (size_t)row * T_ + seg * 8);
        }
    };

    // ---- prologue: Q tiles + KV stage 0 ----
    {
        const __nv_bfloat16* qh = g_Qhi + ((size_t)bh * T_ + qt * 64) * D_;
        const __nv_bfloat16* ql = g_Qlo + ((size_t)bh * T_ + qt * 64) * D_;
        #pragma unroll
        for (int i = 0; i < 4; i++) {
            int idx = tid + i * 128;
            int row = idx >> 3, seg = idx & 7;
            uint32_t off = (uint32_t)row * 128 + ((seg ^ (row & 7)) * 16);
            CP_ASYNC16(sb + ASM_Q + off,        qh + (size_t)row * D_ + seg * 8);
            CP_ASYNC16(sb + ASM_Q + 8192 + off, ql + (size_t)row * D_ + seg * 8);
        }
        issue_kv(0, 0);
        CP_COMMIT(); CP_WAIT0();
        __syncthreads();
    }

    // ---- Q fragments (persistent) ----
    uint32_t qh[4][4], ql[4][4];
    {
        const int row = wid * 16 + (lane & 15);
        const uint32_t rb = (uint32_t)row * 128;
        #pragma unroll
        for (int ks = 0; ks < 4; ks++) {
            int seg = ks * 2 + (lane >> 4);
            uint32_t off = rb + ((seg ^ (row & 7)) * 16);
            ldsm_x4(qh[ks][0], qh[ks][1], qh[ks][2], qh[ks][3], sb + ASM_Q + off);
            ldsm_x4(ql[ks][0], ql[ks][1], ql[ks][2], ql[ks][3], sb + ASM_Q + 8192 + off);
        }
    }

    float m0 = -1e30f, m1 = -1e30f, l0 = 0.f, l1 = 0.f;
    float o[8][4];
    #pragma unroll
    for (int nf = 0; nf < 8; nf++)
        #pragma unroll
        for (int q = 0; q < 4; q++) o[nf][q] = 0.f;

    const int bg = lane >> 3;
    const int brow_lo = ((bg >> 1) * 8) + (lane & 7);
    const int bseg0 = bg & 1;

    for (int st = 0; st < 16; st++) {
        const int buf = st & 1;
        // prefetch next stage
        if (st + 1 < 16) issue_kv(st + 1, buf ^ 1);
        CP_COMMIT();

        const uint32_t kbase = sb + ASM_ST0 + (uint32_t)buf * ASM_STS;
        const uint32_t vbase = kbase + 16384;

        // ---- S = Qhi Khi^T + Qhi Klo^T + Qlo Khi^T ----
        float sacc[8][4];
        #pragma unroll
        for (int nf = 0; nf < 8; nf++)
            #pragma unroll
            for (int q = 0; q < 4; q++) sacc[nf][q] = 0.f;

        #pragma unroll
        for (int ph = 0; ph < 3; ph++) {
            const uint32_t (*aq)[4] = (ph == 2) ? ql : qh;
            const uint32_t kt = kbase + ((ph == 1) ? 8192 : 0);
            #pragma unroll
            for (int ks = 0; ks < 4; ks++) {
                uint32_t bf[8][2];
                #pragma unroll
                for (int nf2 = 0; nf2 < 4; nf2++) {
                    int row = nf2 * 16 + brow_lo;
                    int seg = (ks * 2 + bseg0) ^ (row & 7);
                    uint32_t r0, r1, r2, r3;
                    ldsm_x4(r0, r1, r2, r3, kt + (uint32_t)row * 128 + seg * 16);
                    bf[nf2 * 2 + 0][0] = r0; bf[nf2 * 2 + 0][1] = r1;
                    bf[nf2 * 2 + 1][0] = r2; bf[nf2 * 2 + 1][1] = r3;
                }
                #pragma unroll
                for (int nf = 0; nf < 8; nf++)
                    mma_bf16(sacc[nf], aq[ks], bf[nf]);
            }
        }

        // ---- online softmax ----
        float mx0 = m0, mx1 = m1;
        #pragma unroll
        for (int nf = 0; nf < 8; nf++) {
            mx0 = fmaxf(mx0, fmaxf(sacc[nf][0], sacc[nf][1]));
            mx1 = fmaxf(mx1, fmaxf(sacc[nf][2], sacc[nf][3]));
        }
        mx0 = fmaxf(mx0, __shfl_xor_sync(0xffffffffu, mx0, 1));
        mx0 = fmaxf(mx0, __shfl_xor_sync(0xffffffffu, mx0, 2));
        mx1 = fmaxf(mx1, __shfl_xor_sync(0xffffffffu, mx1, 1));
        mx1 = fmaxf(mx1, __shfl_xor_sync(0xffffffffu, mx1, 2));

        const float c0 = __expf(m0 - mx0);
        const float c1 = __expf(m1 - mx1);
        m0 = mx0; m1 = mx1;
        l0 *= c0; l1 *= c1;
        #pragma unroll
        for (int nf = 0; nf < 8; nf++) {
            o[nf][0] *= c0; o[nf][1] *= c0;
            o[nf][2] *= c1; o[nf][3] *= c1;
        }
        #pragma unroll
        for (int nf = 0; nf < 8; nf++) {
            float e0 = __expf(sacc[nf][0] - m0);
            float e1 = __expf(sacc[nf][1] - m0);
            float e2 = __expf(sacc[nf][2] - m1);
            float e3 = __expf(sacc[nf][3] - m1);
            l0 += e0 + e1; l1 += e2 + e3;
            sacc[nf][0] = e0; sacc[nf][1] = e1;
            sacc[nf][2] = e2; sacc[nf][3] = e3;
        }

        // ---- P -> bf16 hi/lo A-fragments ----
        uint32_t phi[4][4], plo[4][4];
        #pragma unroll
        for (int ks = 0; ks < 4; ks++) {
            phi[ks][0] = pack_bf16(sacc[2 * ks][0],     sacc[2 * ks][1]);
            phi[ks][1] = pack_bf16(sacc[2 * ks][2],     sacc[2 * ks][3]);
            phi[ks][2] = pack_bf16(sacc[2 * ks + 1][0], sacc[2 * ks + 1][1]);
            phi[ks][3] = pack_bf16(sacc[2 * ks + 1][2], sacc[2 * ks + 1][3]);
            plo[ks][0] = pack_bf16_lo(sacc[2 * ks][0],     sacc[2 * ks][1],     phi[ks][0]);
            plo[ks][1] = pack_bf16_lo(sacc[2 * ks][2],     sacc[2 * ks][3],     phi[ks][1]);
            plo[ks][2] = pack_bf16_lo(sacc[2 * ks + 1][0], sacc[2 * ks + 1][1], phi[ks][2]);
            plo[ks][3] = pack_bf16_lo(sacc[2 * ks + 1][2], sacc[2 * ks + 1][3], phi[ks][3]);
        }

        // ---- O += Phi Vhi + Phi Vlo + Plo Vhi ----
        #pragma unroll
        for (int ph = 0; ph < 3; ph++) {
            const uint32_t (*ap)[4] = (ph == 2) ? plo : phi;
            const uint32_t vt = vbase + ((ph == 1) ? 8192 : 0);
            #pragma unroll
            for (int ks = 0; ks < 4; ks++) {
                uint32_t bf[8][2];
                #pragma unroll
                for (int nf2 = 0; nf2 < 4; nf2++) {
                    int row = nf2 * 16 + brow_lo;
                    int seg = (ks * 2 + bseg0) ^ (row & 7);
                    uint32_t r0, r1, r2, r3;
                    ldsm_x4(r0, r1, r2, r3, vt + (uint32_t)row * 128 + seg * 16);
                    bf[nf2 * 2 + 0][0] = r0; bf[nf2 * 2 + 0][1] = r1;
                    bf[nf2 * 2 + 1][0] = r2; bf[nf2 * 2 + 1][1] = r3;
                }
                #pragma unroll
                for (int nf = 0; nf < 8; nf++)
                    mma_bf16(o[nf], ap[ks], bf[nf]);
            }
        }

        CP_WAIT0();
        __syncthreads();
    }

    // ---- finalize ----
    l0 += __shfl_xor_sync(0xffffffffu, l0, 1);
    l0 += __shfl_xor_sync(0xffffffffu, l0, 2);
    l1 += __shfl_xor_sync(0xffffffffu, l1, 1);
    l1 += __shfl_xor_sync(0xffffffffu, l1, 2);
    const float inv0 = 1.f / l0;
    const float inv1 = 1.f / l1;

    const int t0 = qt * 64 + wid * 16 + (lane >> 2);
    const int b = bh >> 4, h = bh & 15;
    float* base0 = g_C + ((size_t)(b * T_ + t0)) * E_ + h * D_ + (lane & 3) * 2;
    float* base1 = base0 + (size_t)8 * E_;
    #pragma unroll
    for (int nf = 0; nf < 8; nf++) {
        float2 v0 = make_float2(o[nf][0] * inv0, o[nf][1] * inv0);
        float2 v1 = make_float2(o[nf][2] * inv1, o[nf][3] * inv1);
        *reinterpret_cast<float2*>(base0 + nf * 8) = v0;
        *reinterpret_cast<float2*>(base1 + nf * 8) = v1;
    }
}

// ---------------- launch ----------------
extern "C" void kernel_launch(void* const* d_in, const int* in_sizes, int n_in,
                              void* d_out, int out_size)
{
    const float* query = (const float*)d_in[0];
    const float* key   = (const float*)d_in[1];
    const float* value = (const float*)d_in[2];
    const float* wq    = (const float*)d_in[3];
    const float* bq    = (const float*)d_in[4];
    const float* wk    = (const float*)d_in[5];
    const float* bk    = (const float*)d_in[6];
    const float* wv    = (const float*)d_in[7];
    const float* bv    = (const float*)d_in[8];
    const float* wo    = (const float*)d_in[9];
    const float* bo    = (const float*)d_in[10];
    float* out = (float*)d_out;

    float *Q, *K, *V, *C;
    cudaGetSymbolAddress((void**)&Q, g_Q);
    cudaGetSymbolAddress((void**)&K, g_K);
    cudaGetSymbolAddress((void**)&V, g_V);
    cudaGetSymbolAddress((void**)&C, g_C);
    __nv_bfloat16 *Xhi3, *Xlo3, *Whi3, *Wlo3;
    cudaGetSymbolAddress((void**)&Xhi3, g_Xhi3);
    cudaGetSymbolAddress((void**)&Xlo3, g_Xlo3);
    cudaGetSymbolAddress((void**)&Whi3, g_Whi3);
    cudaGetSymbolAddress((void**)&Wlo3, g_Wlo3);

    static bool attr_done = false;
    if (!attr_done) {
        cudaFuncSetAttribute(gemm_qkv, cudaFuncAttributeMaxDynamicSharedMemorySize, GEMM_SMEM);
        cudaFuncSetAttribute(gemm_out, cudaFuncAttributeMaxDynamicSharedMemorySize, GEMM_SMEM);
        cudaFuncSetAttribute(attn_mma, cudaFuncAttributeMaxDynamicSharedMemorySize, ATTN_SMEM);
        attr_done = true;
    }

    const int actn8 = (M_ * E_) / 8;
    const int wn8   = (E_ * E_) / 8;

    // split activations + weights into packed buffers
    split_kernel<<<actn8 / 256, 256>>>(query, Xhi3,                      Xlo3,                      actn8);
    split_kernel<<<actn8 / 256, 256>>>(key,   Xhi3 + (size_t)M_ * E_,    Xlo3 + (size_t)M_ * E_,    actn8);
    split_kernel<<<actn8 / 256, 256>>>(value, Xhi3 + (size_t)2 * M_ * E_, Xlo3 + (size_t)2 * M_ * E_, actn8);
    split_kernel<<<wn8 / 256, 256>>>(wq, Whi3,                       Wlo3,                       wn8);
    split_kernel<<<wn8 / 256, 256>>>(wk, Whi3 + (size_t)E_ * E_,     Wlo3 + (size_t)E_ * E_,     wn8);
    split_kernel<<<wn8 / 256, 256>>>(wv, Whi3 + (size_t)2 * E_ * E_, Wlo3 + (size_t)2 * E_ * E_, wn8);

    // merged QKV projection
    gemm_qkv<<<dim3(E_ / 128, M_ / 128, 3), 256, GEMM_SMEM>>>(bq, bk, bv, Q, K, V);

    int xpos_threads = BH_ * T_ * (D_ / 2);
    xpos_split_kernel<<<xpos_threads / 256, 256>>>();
    vt_split_kernel<<<dim3(BH_, T_ / 64), 256>>>();

    attn_mma<<<dim3(BH_, T_ / 64), 128, ATTN_SMEM>>>();

    // output projection (reuse slot 0 of packed buffers)
    split_kernel<<<actn8 / 256, 256>>>(C, Xhi3, Xlo3, actn8);
    split_kernel<<<wn8 / 256, 256>>>(wo, Whi3, Wlo3, wn8);
    gemm_out<<<dim3(E_ / 128, M_ / 128), 256, GEMM_SMEM>>>(bo, out);
}